// round 13
// baseline (speedup 1.0000x reference)
#include <cuda_runtime.h>
#include <stdint.h>
#include <math.h>
#include <string.h>

#define NB 16
#define RB 128   // reduce blocks per sample

struct SampleRand {
    float c, s, ysign;
    float sh[3];
    float r1[3], r2[3];
};
struct AllRand { SampleRand smp[NB]; };

// ---------------- device scratch (static; no allocation) ----------------
__device__ float g_part[NB][RB][14];
__device__ float g_mean[NB][4];
__device__ float g_std[NB][4];
__device__ float g_off[NB][3];
__device__ unsigned int g_arrive[NB];   // zero-init; self-resetting each replay

// ---------------- kernel 1: transform + partials + fused finalize ----------------
__global__ void __launch_bounds__(256)
k_reduce(const float4* __restrict__ pts, int N, AllRand ar, float* __restrict__ off_out) {
    __shared__ __align__(16) float4 sbuf[8 * 256];   // 32KB staging

    int b = blockIdx.y;
    SampleRand sp = ar.smp[b];
    const float4* p = pts + (size_t)b * N;
    int tid = blockIdx.x * blockDim.x + threadIdx.x;
    const int S = RB * 256;

    bool pr[8];
    uint32_t sbase = (uint32_t)__cvta_generic_to_shared(&sbuf[threadIdx.x]);

    // fire-and-forget: 8 independent LDGSTS.128, zero destination registers held
    #pragma unroll
    for (int k = 0; k < 8; k++) {
        int i = tid + k * S;
        pr[k] = (i < N);
        const float4* g = p + (pr[k] ? i : 0);     // clamped; src_size=0 when invalid
        unsigned src_sz = pr[k] ? 16u : 0u;
        asm volatile("cp.async.cg.shared.global [%0], [%1], 16, %2;"
                     :: "r"(sbase + (unsigned)(k * 256 * 16)), "l"(g), "r"(src_sz));
    }
    asm volatile("cp.async.commit_group;");
    asm volatile("cp.async.wait_group 0;");
    // each thread reads back only its own slots -> no __syncthreads needed

    float s0 = 0.f, s1 = 0.f, s2 = 0.f, s3 = 0.f;
    float q0 = 0.f, q1 = 0.f, q2 = 0.f, q3 = 0.f;
    // min/max in UNSCALED z space; exact since 32*min(z) == min(32*z)
    float mn0 = 3.4e38f, mn1 = 3.4e38f, mn2 = 3.4e38f;
    float mx0 = -3.4e38f, mx1 = -3.4e38f, mx2 = -3.4e38f;

    #pragma unroll
    for (int k = 0; k < 8; k++) {
        if (pr[k]) {
            float4 v = sbuf[threadIdx.x + k * 256];
            float x = v.x, y = sp.ysign * v.y;
            float z0 = x * sp.c - y * sp.s + sp.sh[0];
            float z1 = x * sp.s + y * sp.c + sp.sh[1];
            float z2 = v.z + sp.sh[2];
            s0 += z0; s1 += z1; s2 += z2; s3 += v.w;
            q0 += z0 * z0; q1 += z1 * z1; q2 += z2 * z2; q3 += v.w * v.w;
            mn0 = fminf(mn0, z0); mn1 = fminf(mn1, z1); mn2 = fminf(mn2, z2);
            mx0 = fmaxf(mx0, z0); mx1 = fmaxf(mx1, z1); mx2 = fmaxf(mx2, z2);
        }
    }
    // generic fallback (not executed for N <= 8*S = 262144)
    for (int i = tid + 8 * S; i < N; i += S) {
        float4 v = __ldcg(p + i);
        float x = v.x, y = sp.ysign * v.y;
        float z0 = x * sp.c - y * sp.s + sp.sh[0];
        float z1 = x * sp.s + y * sp.c + sp.sh[1];
        float z2 = v.z + sp.sh[2];
        s0 += z0; s1 += z1; s2 += z2; s3 += v.w;
        q0 += z0 * z0; q1 += z1 * z1; q2 += z2 * z2; q3 += v.w * v.w;
        mn0 = fminf(mn0, z0); mn1 = fminf(mn1, z1); mn2 = fminf(mn2, z2);
        mx0 = fmaxf(mx0, z0); mx1 = fmaxf(mx1, z1); mx2 = fmaxf(mx2, z2);
    }

    #pragma unroll
    for (int o = 16; o; o >>= 1) {
        s0 += __shfl_down_sync(0xFFFFFFFFu, s0, o);
        s1 += __shfl_down_sync(0xFFFFFFFFu, s1, o);
        s2 += __shfl_down_sync(0xFFFFFFFFu, s2, o);
        s3 += __shfl_down_sync(0xFFFFFFFFu, s3, o);
        q0 += __shfl_down_sync(0xFFFFFFFFu, q0, o);
        q1 += __shfl_down_sync(0xFFFFFFFFu, q1, o);
        q2 += __shfl_down_sync(0xFFFFFFFFu, q2, o);
        q3 += __shfl_down_sync(0xFFFFFFFFu, q3, o);
        mn0 = fminf(mn0, __shfl_down_sync(0xFFFFFFFFu, mn0, o));
        mn1 = fminf(mn1, __shfl_down_sync(0xFFFFFFFFu, mn1, o));
        mn2 = fminf(mn2, __shfl_down_sync(0xFFFFFFFFu, mn2, o));
        mx0 = fmaxf(mx0, __shfl_down_sync(0xFFFFFFFFu, mx0, o));
        mx1 = fmaxf(mx1, __shfl_down_sync(0xFFFFFFFFu, mx1, o));
        mx2 = fmaxf(mx2, __shfl_down_sync(0xFFFFFFFFu, mx2, o));
    }

    __shared__ float sred[14][8];
    int w = threadIdx.x >> 5;
    if ((threadIdx.x & 31) == 0) {
        sred[0][w] = s0;  sred[1][w] = s1;  sred[2][w] = s2;  sred[3][w] = s3;
        sred[4][w] = q0;  sred[5][w] = q1;  sred[6][w] = q2;  sred[7][w] = q3;
        sred[8][w] = mn0; sred[9][w] = mn1; sred[10][w] = mn2;
        sred[11][w] = mx0; sred[12][w] = mx1; sred[13][w] = mx2;
    }
    __syncthreads();
    if (threadIdx.x < 14) {
        int k = threadIdx.x;
        float r = sred[k][0];
        if (k < 8)       for (int j = 1; j < 8; j++) r += sred[k][j];
        else if (k < 11) for (int j = 1; j < 8; j++) r = fminf(r, sred[k][j]);
        else             for (int j = 1; j < 8; j++) r = fmaxf(r, sred[k][j]);
        g_part[b][blockIdx.x][k] = r;
    }

    // ---------- fused finalize: last arriving block per sample ----------
    __shared__ bool is_last;
    __syncthreads();        // partial writes done block-wide
    __threadfence();        // executed by ALL threads incl. writers -> device-visible
    __syncthreads();        // fences complete before the arrival atomic
    if (threadIdx.x == 0) {
        unsigned int prev = atomicAdd(&g_arrive[b], 1u);
        is_last = (prev == RB - 1);
        if (is_last) g_arrive[b] = 0;   // self-reset for graph replay
    }
    __syncthreads();
    if (!is_last) return;

    // last block: 256 threads reduce the 128 partial rows (t>=128 neutral)
    int t = threadIdx.x;
    bool have = (t < RB);
    float v[14];
    #pragma unroll
    for (int k = 0; k < 8; k++)  v[k] = have ? g_part[b][t][k] : 0.f;
    #pragma unroll
    for (int k = 8; k < 11; k++) v[k] = have ? g_part[b][t][k] : 3.4e38f;
    #pragma unroll
    for (int k = 11; k < 14; k++) v[k] = have ? g_part[b][t][k] : -3.4e38f;

    double d[8];
    #pragma unroll
    for (int k = 0; k < 8; k++) d[k] = (double)v[k];

    #pragma unroll
    for (int o = 16; o; o >>= 1) {
        #pragma unroll
        for (int k = 0; k < 8; k++)
            d[k] += __shfl_down_sync(0xFFFFFFFFu, d[k], o);
        #pragma unroll
        for (int k = 8; k < 11; k++)
            v[k] = fminf(v[k], __shfl_down_sync(0xFFFFFFFFu, v[k], o));
        #pragma unroll
        for (int k = 11; k < 14; k++)
            v[k] = fmaxf(v[k], __shfl_down_sync(0xFFFFFFFFu, v[k], o));
    }

    __shared__ double ssum[8][8];
    __shared__ float  smm[6][8];
    if ((t & 31) == 0) {
        #pragma unroll
        for (int k = 0; k < 8; k++) ssum[k][w] = d[k];
        #pragma unroll
        for (int k = 0; k < 3; k++) { smm[k][w] = v[8 + k]; smm[3 + k][w] = v[11 + k]; }
    }
    __syncthreads();

    if (t == 0) {
        double n = (double)N;
        #pragma unroll
        for (int k = 0; k < 4; k++) {
            double su = 0.0, sq = 0.0;
            #pragma unroll
            for (int j = 0; j < 8; j++) { su += ssum[k][j]; sq += ssum[4 + k][j]; }
            double mean = su / n;
            double var = (sq - su * su / n) / (n - 1.0);
            if (var < 0.0) var = 0.0;
            g_mean[b][k] = (float)mean;
            g_std[b][k]  = (float)sqrt(var);
        }
        #pragma unroll
        for (int k = 0; k < 3; k++) {
            float m = smm[k][0], M = smm[3 + k][0];
            #pragma unroll
            for (int j = 1; j < 8; j++) { m = fminf(m, smm[k][j]); M = fmaxf(M, smm[3 + k][j]); }
            m *= 32.0f; M *= 32.0f;   // exact: 32*min(z) == min(32*z)
            float q = M - m;
            float off = -m + fmaxf(512.0f - q - 0.001f, 0.0f) * sp.r1[k]
                           + fminf(512.0f - q + 0.001f, 0.0f) * sp.r2[k];
            g_off[b][k] = off;
            off_out[b * 3 + k] = off;
        }
        __threadfence();
    }
}

// ---------------- kernel 2: elementwise outputs, ILP=2, streaming hints ----------------
#define FB  256
#define PPB 512   // points per block (2 per thread)

__global__ void __launch_bounds__(FB)
k_final(const float4* __restrict__ pts,
        const int* __restrict__ tgt,
        const int* __restrict__ msk,
        int N, AllRand ar,
        float* __restrict__ out_locs,
        float* __restrict__ out_feats,
        float* __restrict__ out_org,
        float* __restrict__ out_lbl,
        float* __restrict__ out_nm) {
    __shared__ __align__(16) float s_org[PPB * 7];

    int b = blockIdx.y;
    int warp = threadIdx.x >> 5, lane = threadIdx.x & 31;
    int base = blockIdx.x * PPB;

    SampleRand sp = ar.smp[b];
    float mean0 = g_mean[b][0], mean1 = g_mean[b][1], mean2 = g_mean[b][2], mean3 = g_mean[b][3];
    float istd0 = 1.f / g_std[b][0], istd1 = 1.f / g_std[b][1],
          istd2 = 1.f / g_std[b][2], istd3 = 1.f / g_std[b][3];
    float off0 = g_off[b][0], off1 = g_off[b][1], off2 = g_off[b][2];

    int i0 = base + threadIdx.x;
    int i1 = i0 + FB;
    bool a0 = (i0 < N), a1 = (i1 < N);
    size_t pbase = (size_t)b * N;
    size_t p0 = pbase + i0, p1 = pbase + i1;

    // front-batched evict-first loads (6 independent requests)
    float4 v0 = a0 ? __ldcs(pts + p0) : make_float4(0.f, 0.f, 0.f, 0.f);
    float4 v1 = a1 ? __ldcs(pts + p1) : make_float4(0.f, 0.f, 0.f, 0.f);
    int m0 = a0 ? __ldcs(msk + p0) : 0;
    int m1 = a1 ? __ldcs(msk + p1) : 0;
    int t0 = a0 ? __ldcs(tgt + p0) : 0;
    int t1 = a1 ? __ldcs(tgt + p1) : 0;

    #pragma unroll
    for (int t = 0; t < 2; t++) {
        bool act = t ? a1 : a0;
        if (!act) continue;
        float4 v = t ? v1 : v0;
        int m = t ? m1 : m0;
        int tg = t ? t1 : t0;
        size_t pi = t ? p1 : p0;
        int srow = threadIdx.x + t * FB;

        float x = v.x, y = sp.ysign * v.y;
        float z0 = x * sp.c - y * sp.s + sp.sh[0];
        float z1 = x * sp.s + y * sp.c + sp.sh[1];
        float z2 = v.z + sp.sh[2];

        float f0 = (z0 - mean0) * istd0;
        float f1 = (z1 - mean1) * istd1;
        float f2 = (z2 - mean2) * istd2;
        float f3 = (v.w - mean3) * istd3;

        float a0f = 32.f * z0 + off0;
        float a1f = 32.f * z1 + off1;
        float a2f = 32.f * z2 + off2;

        bool valid = (a0f >= 0.f) && (a1f >= 0.f) && (a2f >= 0.f) &&
                     (a0f < 512.f) && (a1f < 512.f) && (a2f < 512.f) && (m > 0);

        float4 lo;
        lo.x = valid ? (float)(int)a0f : 0.f;
        lo.y = valid ? (float)(int)a1f : 0.f;
        lo.z = valid ? (float)(int)a2f : 0.f;
        lo.w = (float)b;
        __stcs(reinterpret_cast<float4*>(out_locs) + pi, lo);

        float4 ft;
        ft.x = valid ? f0 : 0.f;
        ft.y = valid ? f1 : 0.f;
        ft.z = valid ? f2 : 0.f;
        ft.w = valid ? f3 : 0.f;
        __stcs(reinterpret_cast<float4*>(out_feats) + pi, ft);

        __stcs(out_lbl + pi, valid ? (float)tg : 0.f);
        __stcs(out_nm + pi, (float)(valid ? m : 0));

        float* so = s_org + srow * 7;
        so[0] = z0; so[1] = z1; so[2] = z2;
        so[3] = f0; so[4] = f1; so[5] = f2; so[6] = f3;
    }
    __syncwarp();

    // warp-local coalesced streaming flush of its two 32x7 org tiles
    #pragma unroll
    for (int t = 0; t < 2; t++) {
        int wrow = t * FB + warp * 32;
        int gpt  = base + wrow;
        int cnt = N - gpt;
        if (cnt > 32) cnt = 32;
        if (cnt > 0) {
            int nf = cnt * 7;
            float* dst = out_org + (pbase + gpt) * 7;
            const float* src = s_org + wrow * 7;
            int nq = nf >> 2;
            const float4* s4 = (const float4*)src;
            float4* d4 = (float4*)dst;
            for (int idx = lane; idx < nq; idx += 32) __stcs(d4 + idx, s4[idx]);
            int rem = nf & 3;
            if (lane < rem) __stcs(dst + nq * 4 + lane, src[nq * 4 + lane]);
        }
    }
}

// =====================================================================
// Host side: exact JAX threefry-2x32 PRNG replication for key(42)
// PARTITIONABLE mode:
//   split(key, n):   key_j = (o0, o1) of threefry(key, counts=(0, j))
//   random_bits 32:  bits_i = o0 ^ o1 of threefry(key, counts=(0, i))
// =====================================================================
static inline uint32_t rotl32(uint32_t x, int r) { return (x << r) | (x >> (32 - r)); }

static void tf2x32(uint32_t k0, uint32_t k1, uint32_t x0, uint32_t x1,
                   uint32_t* o0, uint32_t* o1) {
    uint32_t ks2 = k0 ^ k1 ^ 0x1BD11BDAu;
    static const int R0[4] = {13, 15, 26, 6}, R1[4] = {17, 29, 16, 24};
    x0 += k0; x1 += k1;
    for (int i = 0; i < 4; i++) { x0 += x1; x1 = rotl32(x1, R0[i]); x1 ^= x0; }
    x0 += k1; x1 += ks2 + 1u;
    for (int i = 0; i < 4; i++) { x0 += x1; x1 = rotl32(x1, R1[i]); x1 ^= x0; }
    x0 += ks2; x1 += k0 + 2u;
    for (int i = 0; i < 4; i++) { x0 += x1; x1 = rotl32(x1, R0[i]); x1 ^= x0; }
    x0 += k0; x1 += k1 + 3u;
    for (int i = 0; i < 4; i++) { x0 += x1; x1 = rotl32(x1, R1[i]); x1 ^= x0; }
    x0 += k1; x1 += ks2 + 4u;
    for (int i = 0; i < 4; i++) { x0 += x1; x1 = rotl32(x1, R0[i]); x1 ^= x0; }
    x0 += ks2; x1 += k0 + 5u;
    *o0 = x0; *o1 = x1;
}

static inline uint32_t rb32(uint32_t k0, uint32_t k1, uint32_t hi, uint32_t lo) {
    uint32_t a, b;
    tf2x32(k0, k1, hi, lo, &a, &b);
    return a ^ b;
}

static inline float u01(uint32_t bits) {
    union { uint32_t u; float f; } c;
    c.u = (bits >> 9) | 0x3f800000u;
    return c.f - 1.0f;
}

static float unif_scalar(uint32_t k0, uint32_t k1) {
    float v = u01(rb32(k0, k1, 0u, 0u));
    return v < 0.f ? 0.f : v;
}

static void unif3(uint32_t k0, uint32_t k1, float u[3]) {
    for (uint32_t i = 0; i < 3; i++) u[i] = u01(rb32(k0, k1, 0u, i));
}

static float erfinv_f(float x) {
    float w = -log1pf(-x * x);
    float p;
    if (w < 5.0f) {
        w -= 2.5f;
        p = 2.81022636e-08f;
        p = fmaf(p, w, 3.43273939e-07f);
        p = fmaf(p, w, -3.5233877e-06f);
        p = fmaf(p, w, -4.39150654e-06f);
        p = fmaf(p, w, 0.00021858087f);
        p = fmaf(p, w, -0.00125372503f);
        p = fmaf(p, w, -0.00417768164f);
        p = fmaf(p, w, 0.246640727f);
        p = fmaf(p, w, 1.50140941f);
    } else {
        w = sqrtf(w) - 3.0f;
        p = -0.000200214257f;
        p = fmaf(p, w, 0.000100950558f);
        p = fmaf(p, w, 0.00134934322f);
        p = fmaf(p, w, -0.00367342844f);
        p = fmaf(p, w, 0.00573950773f);
        p = fmaf(p, w, -0.0076224613f);
        p = fmaf(p, w, 0.00943887047f);
        p = fmaf(p, w, 1.00167406f);
        p = fmaf(p, w, 2.83297682f);
    }
    return p * x;
}

static void normal3(uint32_t k0, uint32_t k1, float n[3]) {
    float u[3];
    unif3(k0, k1, u);
    const float lo = -0.99999994f;
    const float sqrt2 = 1.41421354f;
    for (int i = 0; i < 3; i++) {
        float v = u[i] * (1.0f - lo) + lo;
        if (v < lo) v = lo;
        n[i] = sqrt2 * erfinv_f(v);
    }
}

static AllRand make_allrand() {
    uint32_t keyw[80][2];
    for (uint32_t j = 0; j < 80; j++) {
        tf2x32(0u, 42u, 0u, j, &keyw[j][0], &keyw[j][1]);
    }
    AllRand ar;
    const float var3[3] = {0.1f, 0.1f, 0.05f};
    for (int b = 0; b < NB; b++) {
        uint32_t K[5][2];
        for (int t = 0; t < 5; t++) {
            K[t][0] = keyw[5 * b + t][0];
            K[t][1] = keyw[5 * b + t][1];
        }
        float uf = unif_scalar(K[0][0], K[0][1]);
        ar.smp[b].ysign = (uf < 0.25f) ? -1.f : 1.f;

        float ur = unif_scalar(K[1][0], K[1][1]);
        float ang = (ur - 0.5f) * (float)(30.0 / 180.0) * (float)M_PI;
        ar.smp[b].c = (float)cos((double)ang);
        ar.smp[b].s = (float)sin((double)ang);

        float nrm[3];
        normal3(K[2][0], K[2][1], nrm);
        for (int k = 0; k < 3; k++) ar.smp[b].sh[k] = nrm[k] * var3[k];

        unif3(K[3][0], K[3][1], ar.smp[b].r1);
        unif3(K[4][0], K[4][1], ar.smp[b].r2);
    }
    return ar;
}

extern "C" void kernel_launch(void* const* d_in, const int* in_sizes, int n_in,
                              void* d_out, int out_size) {
    const float4* pts = (const float4*)d_in[0];
    const int* tgt = (const int*)d_in[1];   // jnp.int64 under x64-disabled JAX -> int32
    const int* msk = (const int*)d_in[2];
    int N = in_sizes[0] / (NB * 4);

    AllRand ar = make_allrand();

    float* out = (float*)d_out;
    size_t bn = (size_t)NB * (size_t)N;
    float* o_locs  = out;
    float* o_feats = out + bn * 4;
    float* o_org   = out + bn * 8;
    float* o_lbl   = out + bn * 15;
    float* o_nm    = out + bn * 16;
    float* o_off   = out + bn * 17;

    k_reduce<<<dim3(RB, NB), 256>>>(pts, N, ar, o_off);
    k_final<<<dim3((N + PPB - 1) / PPB, NB), FB>>>(pts, tgt, msk, N, ar,
                                                   o_locs, o_feats, o_org, o_lbl, o_nm);
    (void)n_in; (void)out_size;
}

// round 14
// speedup vs baseline: 1.0591x; 1.0591x over previous
#include <cuda_runtime.h>
#include <stdint.h>
#include <math.h>
#include <string.h>

#define NB 16
#define RB 128   // reduce blocks per sample

struct SampleRand {
    float c, s, ysign;
    float sh[3];
    float r1[3], r2[3];
};
struct AllRand { SampleRand smp[NB]; };

// ---------------- device scratch (static; no allocation) ----------------
__device__ float g_part[NB][RB][14];
__device__ float g_mean[NB][4];
__device__ float g_std[NB][4];
__device__ float g_off[NB][3];

// ---------------- kernel 1: transform + per-block partial reductions ----------------
// cp.async version: loads land in smem, not registers -> low regs, high occ, MLP=8.
__global__ void __launch_bounds__(256)
k_reduce(const float4* __restrict__ pts, int N, AllRand ar) {
    __shared__ __align__(16) float4 sbuf[8 * 256];   // 32KB staging

    int b = blockIdx.y;
    SampleRand sp = ar.smp[b];
    const float4* p = pts + (size_t)b * N;
    int tid = blockIdx.x * blockDim.x + threadIdx.x;
    const int S = RB * 256;

    bool pr[8];
    uint32_t sbase = (uint32_t)__cvta_generic_to_shared(&sbuf[threadIdx.x]);

    // fire-and-forget: 8 independent LDGSTS.128, zero destination registers held
    #pragma unroll
    for (int k = 0; k < 8; k++) {
        int i = tid + k * S;
        pr[k] = (i < N);
        const float4* g = p + (pr[k] ? i : 0);     // clamped; src_size=0 when invalid
        unsigned src_sz = pr[k] ? 16u : 0u;
        asm volatile("cp.async.cg.shared.global [%0], [%1], 16, %2;"
                     :: "r"(sbase + (unsigned)(k * 256 * 16)), "l"(g), "r"(src_sz));
    }
    asm volatile("cp.async.commit_group;");
    asm volatile("cp.async.wait_group 0;");
    // each thread reads back only its own slots -> no __syncthreads needed

    float s0 = 0.f, s1 = 0.f, s2 = 0.f, s3 = 0.f;
    float q0 = 0.f, q1 = 0.f, q2 = 0.f, q3 = 0.f;
    // min/max in UNSCALED z space; exact since 32*min(z) == min(32*z)
    float mn0 = 3.4e38f, mn1 = 3.4e38f, mn2 = 3.4e38f;
    float mx0 = -3.4e38f, mx1 = -3.4e38f, mx2 = -3.4e38f;

    #pragma unroll
    for (int k = 0; k < 8; k++) {
        if (pr[k]) {
            float4 v = sbuf[threadIdx.x + k * 256];
            float x = v.x, y = sp.ysign * v.y;
            float z0 = x * sp.c - y * sp.s + sp.sh[0];
            float z1 = x * sp.s + y * sp.c + sp.sh[1];
            float z2 = v.z + sp.sh[2];
            s0 += z0; s1 += z1; s2 += z2; s3 += v.w;
            q0 += z0 * z0; q1 += z1 * z1; q2 += z2 * z2; q3 += v.w * v.w;
            mn0 = fminf(mn0, z0); mn1 = fminf(mn1, z1); mn2 = fminf(mn2, z2);
            mx0 = fmaxf(mx0, z0); mx1 = fmaxf(mx1, z1); mx2 = fmaxf(mx2, z2);
        }
    }
    // generic fallback (not executed for N <= 8*S = 262144)
    for (int i = tid + 8 * S; i < N; i += S) {
        float4 v = __ldcg(p + i);
        float x = v.x, y = sp.ysign * v.y;
        float z0 = x * sp.c - y * sp.s + sp.sh[0];
        float z1 = x * sp.s + y * sp.c + sp.sh[1];
        float z2 = v.z + sp.sh[2];
        s0 += z0; s1 += z1; s2 += z2; s3 += v.w;
        q0 += z0 * z0; q1 += z1 * z1; q2 += z2 * z2; q3 += v.w * v.w;
        mn0 = fminf(mn0, z0); mn1 = fminf(mn1, z1); mn2 = fminf(mn2, z2);
        mx0 = fmaxf(mx0, z0); mx1 = fmaxf(mx1, z1); mx2 = fmaxf(mx2, z2);
    }

    #pragma unroll
    for (int o = 16; o; o >>= 1) {
        s0 += __shfl_down_sync(0xFFFFFFFFu, s0, o);
        s1 += __shfl_down_sync(0xFFFFFFFFu, s1, o);
        s2 += __shfl_down_sync(0xFFFFFFFFu, s2, o);
        s3 += __shfl_down_sync(0xFFFFFFFFu, s3, o);
        q0 += __shfl_down_sync(0xFFFFFFFFu, q0, o);
        q1 += __shfl_down_sync(0xFFFFFFFFu, q1, o);
        q2 += __shfl_down_sync(0xFFFFFFFFu, q2, o);
        q3 += __shfl_down_sync(0xFFFFFFFFu, q3, o);
        mn0 = fminf(mn0, __shfl_down_sync(0xFFFFFFFFu, mn0, o));
        mn1 = fminf(mn1, __shfl_down_sync(0xFFFFFFFFu, mn1, o));
        mn2 = fminf(mn2, __shfl_down_sync(0xFFFFFFFFu, mn2, o));
        mx0 = fmaxf(mx0, __shfl_down_sync(0xFFFFFFFFu, mx0, o));
        mx1 = fmaxf(mx1, __shfl_down_sync(0xFFFFFFFFu, mx1, o));
        mx2 = fmaxf(mx2, __shfl_down_sync(0xFFFFFFFFu, mx2, o));
    }

    __shared__ float sred[14][8];
    int w = threadIdx.x >> 5;
    if ((threadIdx.x & 31) == 0) {
        sred[0][w] = s0;  sred[1][w] = s1;  sred[2][w] = s2;  sred[3][w] = s3;
        sred[4][w] = q0;  sred[5][w] = q1;  sred[6][w] = q2;  sred[7][w] = q3;
        sred[8][w] = mn0; sred[9][w] = mn1; sred[10][w] = mn2;
        sred[11][w] = mx0; sred[12][w] = mx1; sred[13][w] = mx2;
    }
    __syncthreads();
    if (threadIdx.x < 14) {
        int k = threadIdx.x;
        float r = sred[k][0];
        if (k < 8)       for (int j = 1; j < 8; j++) r += sred[k][j];
        else if (k < 11) for (int j = 1; j < 8; j++) r = fminf(r, sred[k][j]);
        else             for (int j = 1; j < 8; j++) r = fmaxf(r, sred[k][j]);
        g_part[b][blockIdx.x][k] = r;
    }
}

// ---------------- kernel 2: final reduce + stats + offsets ----------------
__global__ void __launch_bounds__(RB)
k_mid(int N, AllRand ar, float* __restrict__ off_out) {
    int b = blockIdx.x;
    int t = threadIdx.x;

    float v[14];
    #pragma unroll
    for (int k = 0; k < 14; k++) v[k] = g_part[b][t][k];

    __shared__ double ssum[8][4];
    __shared__ float  smm[6][4];

    double d[8];
    #pragma unroll
    for (int k = 0; k < 8; k++) d[k] = (double)v[k];

    #pragma unroll
    for (int o = 16; o; o >>= 1) {
        #pragma unroll
        for (int k = 0; k < 8; k++)
            d[k] += __shfl_down_sync(0xFFFFFFFFu, d[k], o);
        #pragma unroll
        for (int k = 8; k < 11; k++)
            v[k] = fminf(v[k], __shfl_down_sync(0xFFFFFFFFu, v[k], o));
        #pragma unroll
        for (int k = 11; k < 14; k++)
            v[k] = fmaxf(v[k], __shfl_down_sync(0xFFFFFFFFu, v[k], o));
    }
    int w = t >> 5;
    if ((t & 31) == 0) {
        #pragma unroll
        for (int k = 0; k < 4; k++) { ssum[w][k] = d[k]; ssum[w + 4][k] = d[k + 4]; }
        #pragma unroll
        for (int k = 0; k < 3; k++) { smm[k][w] = v[8 + k]; smm[3 + k][w] = v[11 + k]; }
    }
    __syncthreads();

    if (t == 0) {
        double n = (double)N;
        SampleRand sp = ar.smp[b];
        #pragma unroll
        for (int k = 0; k < 4; k++) {
            double su = ssum[0][k] + ssum[1][k] + ssum[2][k] + ssum[3][k];
            double sq = ssum[4][k] + ssum[5][k] + ssum[6][k] + ssum[7][k];
            double mean = su / n;
            double var = (sq - su * su / n) / (n - 1.0);
            if (var < 0.0) var = 0.0;
            g_mean[b][k] = (float)mean;
            g_std[b][k]  = (float)sqrt(var);
        }
        #pragma unroll
        for (int k = 0; k < 3; k++) {
            // scale back: 32*min(z) == min(32*z) exactly (power-of-2)
            float m = 32.0f * fminf(fminf(smm[k][0], smm[k][1]), fminf(smm[k][2], smm[k][3]));
            float M = 32.0f * fmaxf(fmaxf(smm[3 + k][0], smm[3 + k][1]), fmaxf(smm[3 + k][2], smm[3 + k][3]));
            float q = M - m;
            float off = -m + fmaxf(512.0f - q - 0.001f, 0.0f) * sp.r1[k]
                           + fminf(512.0f - q + 0.001f, 0.0f) * sp.r2[k];
            g_off[b][k] = off;
            off_out[b * 3 + k] = off;
        }
    }
}

// ---------------- kernel 3: elementwise outputs, ILP=2, streaming hints ----------------
#define FB  256
#define PPB 512   // points per block (2 per thread)

__global__ void __launch_bounds__(FB, 6)
k_final(const float4* __restrict__ pts,
        const int* __restrict__ tgt,
        const int* __restrict__ msk,
        int N, AllRand ar,
        float* __restrict__ out_locs,
        float* __restrict__ out_feats,
        float* __restrict__ out_org,
        float* __restrict__ out_lbl,
        float* __restrict__ out_nm) {
    __shared__ __align__(16) float s_org[PPB * 7];

    int b = blockIdx.y;
    int warp = threadIdx.x >> 5, lane = threadIdx.x & 31;
    int base = blockIdx.x * PPB;

    SampleRand sp = ar.smp[b];
    float mean0 = g_mean[b][0], mean1 = g_mean[b][1], mean2 = g_mean[b][2], mean3 = g_mean[b][3];
    float istd0 = 1.f / g_std[b][0], istd1 = 1.f / g_std[b][1],
          istd2 = 1.f / g_std[b][2], istd3 = 1.f / g_std[b][3];
    float off0 = g_off[b][0], off1 = g_off[b][1], off2 = g_off[b][2];

    int i0 = base + threadIdx.x;
    int i1 = i0 + FB;
    bool a0 = (i0 < N), a1 = (i1 < N);
    size_t pbase = (size_t)b * N;
    size_t p0 = pbase + i0, p1 = pbase + i1;

    // front-batched evict-first loads (6 independent requests)
    float4 v0 = a0 ? __ldcs(pts + p0) : make_float4(0.f, 0.f, 0.f, 0.f);
    float4 v1 = a1 ? __ldcs(pts + p1) : make_float4(0.f, 0.f, 0.f, 0.f);
    int m0 = a0 ? __ldcs(msk + p0) : 0;
    int m1 = a1 ? __ldcs(msk + p1) : 0;
    int t0 = a0 ? __ldcs(tgt + p0) : 0;
    int t1 = a1 ? __ldcs(tgt + p1) : 0;

    #pragma unroll
    for (int t = 0; t < 2; t++) {
        bool act = t ? a1 : a0;
        if (!act) continue;
        float4 v = t ? v1 : v0;
        int m = t ? m1 : m0;
        int tg = t ? t1 : t0;
        size_t pi = t ? p1 : p0;
        int srow = threadIdx.x + t * FB;

        float x = v.x, y = sp.ysign * v.y;
        float z0 = x * sp.c - y * sp.s + sp.sh[0];
        float z1 = x * sp.s + y * sp.c + sp.sh[1];
        float z2 = v.z + sp.sh[2];

        float f0 = (z0 - mean0) * istd0;
        float f1 = (z1 - mean1) * istd1;
        float f2 = (z2 - mean2) * istd2;
        float f3 = (v.w - mean3) * istd3;

        float a0f = 32.f * z0 + off0;
        float a1f = 32.f * z1 + off1;
        float a2f = 32.f * z2 + off2;

        bool valid = (a0f >= 0.f) && (a1f >= 0.f) && (a2f >= 0.f) &&
                     (a0f < 512.f) && (a1f < 512.f) && (a2f < 512.f) && (m > 0);

        float4 lo;
        lo.x = valid ? (float)(int)a0f : 0.f;
        lo.y = valid ? (float)(int)a1f : 0.f;
        lo.z = valid ? (float)(int)a2f : 0.f;
        lo.w = (float)b;
        __stcs(reinterpret_cast<float4*>(out_locs) + pi, lo);

        float4 ft;
        ft.x = valid ? f0 : 0.f;
        ft.y = valid ? f1 : 0.f;
        ft.z = valid ? f2 : 0.f;
        ft.w = valid ? f3 : 0.f;
        __stcs(reinterpret_cast<float4*>(out_feats) + pi, ft);

        __stcs(out_lbl + pi, valid ? (float)tg : 0.f);
        __stcs(out_nm + pi, (float)(valid ? m : 0));

        float* so = s_org + srow * 7;
        so[0] = z0; so[1] = z1; so[2] = z2;
        so[3] = f0; so[4] = f1; so[5] = f2; so[6] = f3;
    }
    __syncwarp();

    // warp-local coalesced streaming flush of its two 32x7 org tiles
    #pragma unroll
    for (int t = 0; t < 2; t++) {
        int wrow = t * FB + warp * 32;
        int gpt  = base + wrow;
        int cnt = N - gpt;
        if (cnt > 32) cnt = 32;
        if (cnt > 0) {
            int nf = cnt * 7;
            float* dst = out_org + (pbase + gpt) * 7;
            const float* src = s_org + wrow * 7;
            int nq = nf >> 2;
            const float4* s4 = (const float4*)src;
            float4* d4 = (float4*)dst;
            for (int idx = lane; idx < nq; idx += 32) __stcs(d4 + idx, s4[idx]);
            int rem = nf & 3;
            if (lane < rem) __stcs(dst + nq * 4 + lane, src[nq * 4 + lane]);
        }
    }
}

// =====================================================================
// Host side: exact JAX threefry-2x32 PRNG replication for key(42)
// PARTITIONABLE mode:
//   split(key, n):   key_j = (o0, o1) of threefry(key, counts=(0, j))
//   random_bits 32:  bits_i = o0 ^ o1 of threefry(key, counts=(0, i))
// =====================================================================
static inline uint32_t rotl32(uint32_t x, int r) { return (x << r) | (x >> (32 - r)); }

static void tf2x32(uint32_t k0, uint32_t k1, uint32_t x0, uint32_t x1,
                   uint32_t* o0, uint32_t* o1) {
    uint32_t ks2 = k0 ^ k1 ^ 0x1BD11BDAu;
    static const int R0[4] = {13, 15, 26, 6}, R1[4] = {17, 29, 16, 24};
    x0 += k0; x1 += k1;
    for (int i = 0; i < 4; i++) { x0 += x1; x1 = rotl32(x1, R0[i]); x1 ^= x0; }
    x0 += k1; x1 += ks2 + 1u;
    for (int i = 0; i < 4; i++) { x0 += x1; x1 = rotl32(x1, R1[i]); x1 ^= x0; }
    x0 += ks2; x1 += k0 + 2u;
    for (int i = 0; i < 4; i++) { x0 += x1; x1 = rotl32(x1, R0[i]); x1 ^= x0; }
    x0 += k0; x1 += k1 + 3u;
    for (int i = 0; i < 4; i++) { x0 += x1; x1 = rotl32(x1, R1[i]); x1 ^= x0; }
    x0 += k1; x1 += ks2 + 4u;
    for (int i = 0; i < 4; i++) { x0 += x1; x1 = rotl32(x1, R0[i]); x1 ^= x0; }
    x0 += ks2; x1 += k0 + 5u;
    *o0 = x0; *o1 = x1;
}

static inline uint32_t rb32(uint32_t k0, uint32_t k1, uint32_t hi, uint32_t lo) {
    uint32_t a, b;
    tf2x32(k0, k1, hi, lo, &a, &b);
    return a ^ b;
}

static inline float u01(uint32_t bits) {
    union { uint32_t u; float f; } c;
    c.u = (bits >> 9) | 0x3f800000u;
    return c.f - 1.0f;
}

static float unif_scalar(uint32_t k0, uint32_t k1) {
    float v = u01(rb32(k0, k1, 0u, 0u));
    return v < 0.f ? 0.f : v;
}

static void unif3(uint32_t k0, uint32_t k1, float u[3]) {
    for (uint32_t i = 0; i < 3; i++) u[i] = u01(rb32(k0, k1, 0u, i));
}

static float erfinv_f(float x) {
    float w = -log1pf(-x * x);
    float p;
    if (w < 5.0f) {
        w -= 2.5f;
        p = 2.81022636e-08f;
        p = fmaf(p, w, 3.43273939e-07f);
        p = fmaf(p, w, -3.5233877e-06f);
        p = fmaf(p, w, -4.39150654e-06f);
        p = fmaf(p, w, 0.00021858087f);
        p = fmaf(p, w, -0.00125372503f);
        p = fmaf(p, w, -0.00417768164f);
        p = fmaf(p, w, 0.246640727f);
        p = fmaf(p, w, 1.50140941f);
    } else {
        w = sqrtf(w) - 3.0f;
        p = -0.000200214257f;
        p = fmaf(p, w, 0.000100950558f);
        p = fmaf(p, w, 0.00134934322f);
        p = fmaf(p, w, -0.00367342844f);
        p = fmaf(p, w, 0.00573950773f);
        p = fmaf(p, w, -0.0076224613f);
        p = fmaf(p, w, 0.00943887047f);
        p = fmaf(p, w, 1.00167406f);
        p = fmaf(p, w, 2.83297682f);
    }
    return p * x;
}

static void normal3(uint32_t k0, uint32_t k1, float n[3]) {
    float u[3];
    unif3(k0, k1, u);
    const float lo = -0.99999994f;
    const float sqrt2 = 1.41421354f;
    for (int i = 0; i < 3; i++) {
        float v = u[i] * (1.0f - lo) + lo;
        if (v < lo) v = lo;
        n[i] = sqrt2 * erfinv_f(v);
    }
}

static AllRand make_allrand() {
    uint32_t keyw[80][2];
    for (uint32_t j = 0; j < 80; j++) {
        tf2x32(0u, 42u, 0u, j, &keyw[j][0], &keyw[j][1]);
    }
    AllRand ar;
    const float var3[3] = {0.1f, 0.1f, 0.05f};
    for (int b = 0; b < NB; b++) {
        uint32_t K[5][2];
        for (int t = 0; t < 5; t++) {
            K[t][0] = keyw[5 * b + t][0];
            K[t][1] = keyw[5 * b + t][1];
        }
        float uf = unif_scalar(K[0][0], K[0][1]);
        ar.smp[b].ysign = (uf < 0.25f) ? -1.f : 1.f;

        float ur = unif_scalar(K[1][0], K[1][1]);
        float ang = (ur - 0.5f) * (float)(30.0 / 180.0) * (float)M_PI;
        ar.smp[b].c = (float)cos((double)ang);
        ar.smp[b].s = (float)sin((double)ang);

        float nrm[3];
        normal3(K[2][0], K[2][1], nrm);
        for (int k = 0; k < 3; k++) ar.smp[b].sh[k] = nrm[k] * var3[k];

        unif3(K[3][0], K[3][1], ar.smp[b].r1);
        unif3(K[4][0], K[4][1], ar.smp[b].r2);
    }
    return ar;
}

extern "C" void kernel_launch(void* const* d_in, const int* in_sizes, int n_in,
                              void* d_out, int out_size) {
    const float4* pts = (const float4*)d_in[0];
    const int* tgt = (const int*)d_in[1];   // jnp.int64 under x64-disabled JAX -> int32
    const int* msk = (const int*)d_in[2];
    int N = in_sizes[0] / (NB * 4);

    AllRand ar = make_allrand();

    float* out = (float*)d_out;
    size_t bn = (size_t)NB * (size_t)N;
    float* o_locs  = out;
    float* o_feats = out + bn * 4;
    float* o_org   = out + bn * 8;
    float* o_lbl   = out + bn * 15;
    float* o_nm    = out + bn * 16;
    float* o_off   = out + bn * 17;

    k_reduce<<<dim3(RB, NB), 256>>>(pts, N, ar);
    k_mid<<<NB, RB>>>(N, ar, o_off);
    k_final<<<dim3((N + PPB - 1) / PPB, NB), FB>>>(pts, tgt, msk, N, ar,
                                                   o_locs, o_feats, o_org, o_lbl, o_nm);
    (void)n_in; (void)out_size;
}

// round 15
// speedup vs baseline: 1.0865x; 1.0259x over previous
#include <cuda_runtime.h>
#include <stdint.h>
#include <math.h>
#include <string.h>

#define NB 16
#define RB 128   // reduce blocks per sample

struct SampleRand {
    float c, s, ysign;
    float sh[3];
    float r1[3], r2[3];
};
struct AllRand { SampleRand smp[NB]; };

// ---------------- device scratch (static; no allocation) ----------------
__device__ float g_part[NB][RB][14];
__device__ float g_mean[NB][4];
__device__ float g_std[NB][4];
__device__ float g_off[NB][3];

// ---------------- kernel 1: transform + per-block partial reductions ----------------
// cp.async: loads land in smem, not registers -> low regs, high occ, MLP=8.
__global__ void __launch_bounds__(256)
k_reduce(const float4* __restrict__ pts, int N, AllRand ar) {
    __shared__ __align__(16) float4 sbuf[8 * 256];   // 32KB staging

    int b = blockIdx.y;
    SampleRand sp = ar.smp[b];
    const float4* p = pts + (size_t)b * N;
    int tid = blockIdx.x * blockDim.x + threadIdx.x;
    const int S = RB * 256;

    bool pr[8];
    uint32_t sbase = (uint32_t)__cvta_generic_to_shared(&sbuf[threadIdx.x]);

    #pragma unroll
    for (int k = 0; k < 8; k++) {
        int i = tid + k * S;
        pr[k] = (i < N);
        const float4* g = p + (pr[k] ? i : 0);
        unsigned src_sz = pr[k] ? 16u : 0u;
        asm volatile("cp.async.cg.shared.global [%0], [%1], 16, %2;"
                     :: "r"(sbase + (unsigned)(k * 256 * 16)), "l"(g), "r"(src_sz));
    }
    asm volatile("cp.async.commit_group;");
    asm volatile("cp.async.wait_group 0;");

    float s0 = 0.f, s1 = 0.f, s2 = 0.f, s3 = 0.f;
    float q0 = 0.f, q1 = 0.f, q2 = 0.f, q3 = 0.f;
    float mn0 = 3.4e38f, mn1 = 3.4e38f, mn2 = 3.4e38f;
    float mx0 = -3.4e38f, mx1 = -3.4e38f, mx2 = -3.4e38f;

    #pragma unroll
    for (int k = 0; k < 8; k++) {
        if (pr[k]) {
            float4 v = sbuf[threadIdx.x + k * 256];
            float x = v.x, y = sp.ysign * v.y;
            float z0 = x * sp.c - y * sp.s + sp.sh[0];
            float z1 = x * sp.s + y * sp.c + sp.sh[1];
            float z2 = v.z + sp.sh[2];
            s0 += z0; s1 += z1; s2 += z2; s3 += v.w;
            q0 += z0 * z0; q1 += z1 * z1; q2 += z2 * z2; q3 += v.w * v.w;
            mn0 = fminf(mn0, z0); mn1 = fminf(mn1, z1); mn2 = fminf(mn2, z2);
            mx0 = fmaxf(mx0, z0); mx1 = fmaxf(mx1, z1); mx2 = fmaxf(mx2, z2);
        }
    }
    for (int i = tid + 8 * S; i < N; i += S) {
        float4 v = __ldcg(p + i);
        float x = v.x, y = sp.ysign * v.y;
        float z0 = x * sp.c - y * sp.s + sp.sh[0];
        float z1 = x * sp.s + y * sp.c + sp.sh[1];
        float z2 = v.z + sp.sh[2];
        s0 += z0; s1 += z1; s2 += z2; s3 += v.w;
        q0 += z0 * z0; q1 += z1 * z1; q2 += z2 * z2; q3 += v.w * v.w;
        mn0 = fminf(mn0, z0); mn1 = fminf(mn1, z1); mn2 = fminf(mn2, z2);
        mx0 = fmaxf(mx0, z0); mx1 = fmaxf(mx1, z1); mx2 = fmaxf(mx2, z2);
    }

    #pragma unroll
    for (int o = 16; o; o >>= 1) {
        s0 += __shfl_down_sync(0xFFFFFFFFu, s0, o);
        s1 += __shfl_down_sync(0xFFFFFFFFu, s1, o);
        s2 += __shfl_down_sync(0xFFFFFFFFu, s2, o);
        s3 += __shfl_down_sync(0xFFFFFFFFu, s3, o);
        q0 += __shfl_down_sync(0xFFFFFFFFu, q0, o);
        q1 += __shfl_down_sync(0xFFFFFFFFu, q1, o);
        q2 += __shfl_down_sync(0xFFFFFFFFu, q2, o);
        q3 += __shfl_down_sync(0xFFFFFFFFu, q3, o);
        mn0 = fminf(mn0, __shfl_down_sync(0xFFFFFFFFu, mn0, o));
        mn1 = fminf(mn1, __shfl_down_sync(0xFFFFFFFFu, mn1, o));
        mn2 = fminf(mn2, __shfl_down_sync(0xFFFFFFFFu, mn2, o));
        mx0 = fmaxf(mx0, __shfl_down_sync(0xFFFFFFFFu, mx0, o));
        mx1 = fmaxf(mx1, __shfl_down_sync(0xFFFFFFFFu, mx1, o));
        mx2 = fmaxf(mx2, __shfl_down_sync(0xFFFFFFFFu, mx2, o));
    }

    __shared__ float sred[14][8];
    int w = threadIdx.x >> 5;
    if ((threadIdx.x & 31) == 0) {
        sred[0][w] = s0;  sred[1][w] = s1;  sred[2][w] = s2;  sred[3][w] = s3;
        sred[4][w] = q0;  sred[5][w] = q1;  sred[6][w] = q2;  sred[7][w] = q3;
        sred[8][w] = mn0; sred[9][w] = mn1; sred[10][w] = mn2;
        sred[11][w] = mx0; sred[12][w] = mx1; sred[13][w] = mx2;
    }
    __syncthreads();
    if (threadIdx.x < 14) {
        int k = threadIdx.x;
        float r = sred[k][0];
        if (k < 8)       for (int j = 1; j < 8; j++) r += sred[k][j];
        else if (k < 11) for (int j = 1; j < 8; j++) r = fminf(r, sred[k][j]);
        else             for (int j = 1; j < 8; j++) r = fmaxf(r, sred[k][j]);
        g_part[b][blockIdx.x][k] = r;
    }
#if __CUDA_ARCH__ >= 900
    cudaTriggerProgrammaticLaunchCompletion();
#endif
}

// ---------------- kernel 2: final reduce + stats + offsets (PDL dependent) ----------------
__global__ void __launch_bounds__(RB)
k_mid(int N, AllRand ar, float* __restrict__ off_out) {
#if __CUDA_ARCH__ >= 900
    cudaGridDependencySynchronize();   // g_part visible
#endif
    int b = blockIdx.x;
    int t = threadIdx.x;

    float v[14];
    #pragma unroll
    for (int k = 0; k < 14; k++) v[k] = g_part[b][t][k];

    __shared__ double ssum[8][4];
    __shared__ float  smm[6][4];

    double d[8];
    #pragma unroll
    for (int k = 0; k < 8; k++) d[k] = (double)v[k];

    #pragma unroll
    for (int o = 16; o; o >>= 1) {
        #pragma unroll
        for (int k = 0; k < 8; k++)
            d[k] += __shfl_down_sync(0xFFFFFFFFu, d[k], o);
        #pragma unroll
        for (int k = 8; k < 11; k++)
            v[k] = fminf(v[k], __shfl_down_sync(0xFFFFFFFFu, v[k], o));
        #pragma unroll
        for (int k = 11; k < 14; k++)
            v[k] = fmaxf(v[k], __shfl_down_sync(0xFFFFFFFFu, v[k], o));
    }
    int w = t >> 5;
    if ((t & 31) == 0) {
        #pragma unroll
        for (int k = 0; k < 4; k++) { ssum[w][k] = d[k]; ssum[w + 4][k] = d[k + 4]; }
        #pragma unroll
        for (int k = 0; k < 3; k++) { smm[k][w] = v[8 + k]; smm[3 + k][w] = v[11 + k]; }
    }
    __syncthreads();

    if (t == 0) {
        double n = (double)N;
        SampleRand sp = ar.smp[b];
        #pragma unroll
        for (int k = 0; k < 4; k++) {
            double su = ssum[0][k] + ssum[1][k] + ssum[2][k] + ssum[3][k];
            double sq = ssum[4][k] + ssum[5][k] + ssum[6][k] + ssum[7][k];
            double mean = su / n;
            double var = (sq - su * su / n) / (n - 1.0);
            if (var < 0.0) var = 0.0;
            g_mean[b][k] = (float)mean;
            g_std[b][k]  = (float)sqrt(var);
        }
        #pragma unroll
        for (int k = 0; k < 3; k++) {
            float m = 32.0f * fminf(fminf(smm[k][0], smm[k][1]), fminf(smm[k][2], smm[k][3]));
            float M = 32.0f * fmaxf(fmaxf(smm[3 + k][0], smm[3 + k][1]), fmaxf(smm[3 + k][2], smm[3 + k][3]));
            float q = M - m;
            float off = -m + fmaxf(512.0f - q - 0.001f, 0.0f) * sp.r1[k]
                           + fminf(512.0f - q + 0.001f, 0.0f) * sp.r2[k];
            g_off[b][k] = off;
            off_out[b * 3 + k] = off;
        }
    }
#if __CUDA_ARCH__ >= 900
    cudaTriggerProgrammaticLaunchCompletion();
#endif
}

// ---------------- kernel 3: elementwise outputs (PDL dependent; prefetch before sync) ----
#define FB  256
#define PPB 512   // points per block (2 per thread)

__global__ void __launch_bounds__(FB)
k_final(const float4* __restrict__ pts,
        const int* __restrict__ tgt,
        const int* __restrict__ msk,
        int N, AllRand ar,
        float* __restrict__ out_locs,
        float* __restrict__ out_feats,
        float* __restrict__ out_org,
        float* __restrict__ out_lbl,
        float* __restrict__ out_nm) {
    __shared__ __align__(16) float s_org[PPB * 7];

    int b = blockIdx.y;
    int warp = threadIdx.x >> 5, lane = threadIdx.x & 31;
    int base = blockIdx.x * PPB;

    SampleRand sp = ar.smp[b];

    int i0 = base + threadIdx.x;
    int i1 = i0 + FB;
    bool a0 = (i0 < N), a1 = (i1 < N);
    size_t pbase = (size_t)b * N;
    size_t p0 = pbase + i0, p1 = pbase + i1;

    // PDL: these loads do NOT depend on k_mid — issue them before the grid sync
    // so the first wave's DRAM ramp overlaps k_mid execution + launch gap.
    float4 v0 = a0 ? __ldcs(pts + p0) : make_float4(0.f, 0.f, 0.f, 0.f);
    float4 v1 = a1 ? __ldcs(pts + p1) : make_float4(0.f, 0.f, 0.f, 0.f);
    int m0 = a0 ? __ldcs(msk + p0) : 0;
    int m1 = a1 ? __ldcs(msk + p1) : 0;
    int t0 = a0 ? __ldcs(tgt + p0) : 0;
    int t1 = a1 ? __ldcs(tgt + p1) : 0;

#if __CUDA_ARCH__ >= 900
    cudaGridDependencySynchronize();   // g_mean/g_std/g_off visible
#endif

    float mean0 = g_mean[b][0], mean1 = g_mean[b][1], mean2 = g_mean[b][2], mean3 = g_mean[b][3];
    float istd0 = 1.f / g_std[b][0], istd1 = 1.f / g_std[b][1],
          istd2 = 1.f / g_std[b][2], istd3 = 1.f / g_std[b][3];
    float off0 = g_off[b][0], off1 = g_off[b][1], off2 = g_off[b][2];

    #pragma unroll
    for (int t = 0; t < 2; t++) {
        bool act = t ? a1 : a0;
        if (!act) continue;
        float4 v = t ? v1 : v0;
        int m = t ? m1 : m0;
        int tg = t ? t1 : t0;
        size_t pi = t ? p1 : p0;
        int srow = threadIdx.x + t * FB;

        float x = v.x, y = sp.ysign * v.y;
        float z0 = x * sp.c - y * sp.s + sp.sh[0];
        float z1 = x * sp.s + y * sp.c + sp.sh[1];
        float z2 = v.z + sp.sh[2];

        float f0 = (z0 - mean0) * istd0;
        float f1 = (z1 - mean1) * istd1;
        float f2 = (z2 - mean2) * istd2;
        float f3 = (v.w - mean3) * istd3;

        float a0f = 32.f * z0 + off0;
        float a1f = 32.f * z1 + off1;
        float a2f = 32.f * z2 + off2;

        bool valid = (a0f >= 0.f) && (a1f >= 0.f) && (a2f >= 0.f) &&
                     (a0f < 512.f) && (a1f < 512.f) && (a2f < 512.f) && (m > 0);

        float4 lo;
        lo.x = valid ? (float)(int)a0f : 0.f;
        lo.y = valid ? (float)(int)a1f : 0.f;
        lo.z = valid ? (float)(int)a2f : 0.f;
        lo.w = (float)b;
        __stcs(reinterpret_cast<float4*>(out_locs) + pi, lo);

        float4 ft;
        ft.x = valid ? f0 : 0.f;
        ft.y = valid ? f1 : 0.f;
        ft.z = valid ? f2 : 0.f;
        ft.w = valid ? f3 : 0.f;
        __stcs(reinterpret_cast<float4*>(out_feats) + pi, ft);

        __stcs(out_lbl + pi, valid ? (float)tg : 0.f);
        __stcs(out_nm + pi, (float)(valid ? m : 0));

        float* so = s_org + srow * 7;
        so[0] = z0; so[1] = z1; so[2] = z2;
        so[3] = f0; so[4] = f1; so[5] = f2; so[6] = f3;
    }
    __syncwarp();

    // warp-local coalesced streaming flush of its two 32x7 org tiles
    #pragma unroll
    for (int t = 0; t < 2; t++) {
        int wrow = t * FB + warp * 32;
        int gpt  = base + wrow;
        int cnt = N - gpt;
        if (cnt > 32) cnt = 32;
        if (cnt > 0) {
            int nf = cnt * 7;
            float* dst = out_org + (pbase + gpt) * 7;
            const float* src = s_org + wrow * 7;
            int nq = nf >> 2;
            const float4* s4 = (const float4*)src;
            float4* d4 = (float4*)dst;
            for (int idx = lane; idx < nq; idx += 32) __stcs(d4 + idx, s4[idx]);
            int rem = nf & 3;
            if (lane < rem) __stcs(dst + nq * 4 + lane, src[nq * 4 + lane]);
        }
    }
}

// =====================================================================
// Host side: exact JAX threefry-2x32 PRNG replication for key(42)
// PARTITIONABLE mode:
//   split(key, n):   key_j = (o0, o1) of threefry(key, counts=(0, j))
//   random_bits 32:  bits_i = o0 ^ o1 of threefry(key, counts=(0, i))
// =====================================================================
static inline uint32_t rotl32(uint32_t x, int r) { return (x << r) | (x >> (32 - r)); }

static void tf2x32(uint32_t k0, uint32_t k1, uint32_t x0, uint32_t x1,
                   uint32_t* o0, uint32_t* o1) {
    uint32_t ks2 = k0 ^ k1 ^ 0x1BD11BDAu;
    static const int R0[4] = {13, 15, 26, 6}, R1[4] = {17, 29, 16, 24};
    x0 += k0; x1 += k1;
    for (int i = 0; i < 4; i++) { x0 += x1; x1 = rotl32(x1, R0[i]); x1 ^= x0; }
    x0 += k1; x1 += ks2 + 1u;
    for (int i = 0; i < 4; i++) { x0 += x1; x1 = rotl32(x1, R1[i]); x1 ^= x0; }
    x0 += ks2; x1 += k0 + 2u;
    for (int i = 0; i < 4; i++) { x0 += x1; x1 = rotl32(x1, R0[i]); x1 ^= x0; }
    x0 += k0; x1 += k1 + 3u;
    for (int i = 0; i < 4; i++) { x0 += x1; x1 = rotl32(x1, R1[i]); x1 ^= x0; }
    x0 += k1; x1 += ks2 + 4u;
    for (int i = 0; i < 4; i++) { x0 += x1; x1 = rotl32(x1, R0[i]); x1 ^= x0; }
    x0 += ks2; x1 += k0 + 5u;
    *o0 = x0; *o1 = x1;
}

static inline uint32_t rb32(uint32_t k0, uint32_t k1, uint32_t hi, uint32_t lo) {
    uint32_t a, b;
    tf2x32(k0, k1, hi, lo, &a, &b);
    return a ^ b;
}

static inline float u01(uint32_t bits) {
    union { uint32_t u; float f; } c;
    c.u = (bits >> 9) | 0x3f800000u;
    return c.f - 1.0f;
}

static float unif_scalar(uint32_t k0, uint32_t k1) {
    float v = u01(rb32(k0, k1, 0u, 0u));
    return v < 0.f ? 0.f : v;
}

static void unif3(uint32_t k0, uint32_t k1, float u[3]) {
    for (uint32_t i = 0; i < 3; i++) u[i] = u01(rb32(k0, k1, 0u, i));
}

static float erfinv_f(float x) {
    float w = -log1pf(-x * x);
    float p;
    if (w < 5.0f) {
        w -= 2.5f;
        p = 2.81022636e-08f;
        p = fmaf(p, w, 3.43273939e-07f);
        p = fmaf(p, w, -3.5233877e-06f);
        p = fmaf(p, w, -4.39150654e-06f);
        p = fmaf(p, w, 0.00021858087f);
        p = fmaf(p, w, -0.00125372503f);
        p = fmaf(p, w, -0.00417768164f);
        p = fmaf(p, w, 0.246640727f);
        p = fmaf(p, w, 1.50140941f);
    } else {
        w = sqrtf(w) - 3.0f;
        p = -0.000200214257f;
        p = fmaf(p, w, 0.000100950558f);
        p = fmaf(p, w, 0.00134934322f);
        p = fmaf(p, w, -0.00367342844f);
        p = fmaf(p, w, 0.00573950773f);
        p = fmaf(p, w, -0.0076224613f);
        p = fmaf(p, w, 0.00943887047f);
        p = fmaf(p, w, 1.00167406f);
        p = fmaf(p, w, 2.83297682f);
    }
    return p * x;
}

static void normal3(uint32_t k0, uint32_t k1, float n[3]) {
    float u[3];
    unif3(k0, k1, u);
    const float lo = -0.99999994f;
    const float sqrt2 = 1.41421354f;
    for (int i = 0; i < 3; i++) {
        float v = u[i] * (1.0f - lo) + lo;
        if (v < lo) v = lo;
        n[i] = sqrt2 * erfinv_f(v);
    }
}

static AllRand make_allrand() {
    uint32_t keyw[80][2];
    for (uint32_t j = 0; j < 80; j++) {
        tf2x32(0u, 42u, 0u, j, &keyw[j][0], &keyw[j][1]);
    }
    AllRand ar;
    const float var3[3] = {0.1f, 0.1f, 0.05f};
    for (int b = 0; b < NB; b++) {
        uint32_t K[5][2];
        for (int t = 0; t < 5; t++) {
            K[t][0] = keyw[5 * b + t][0];
            K[t][1] = keyw[5 * b + t][1];
        }
        float uf = unif_scalar(K[0][0], K[0][1]);
        ar.smp[b].ysign = (uf < 0.25f) ? -1.f : 1.f;

        float ur = unif_scalar(K[1][0], K[1][1]);
        float ang = (ur - 0.5f) * (float)(30.0 / 180.0) * (float)M_PI;
        ar.smp[b].c = (float)cos((double)ang);
        ar.smp[b].s = (float)sin((double)ang);

        float nrm[3];
        normal3(K[2][0], K[2][1], nrm);
        for (int k = 0; k < 3; k++) ar.smp[b].sh[k] = nrm[k] * var3[k];

        unif3(K[3][0], K[3][1], ar.smp[b].r1);
        unif3(K[4][0], K[4][1], ar.smp[b].r2);
    }
    return ar;
}

extern "C" void kernel_launch(void* const* d_in, const int* in_sizes, int n_in,
                              void* d_out, int out_size) {
    const float4* pts = (const float4*)d_in[0];
    const int* tgt = (const int*)d_in[1];   // jnp.int64 under x64-disabled JAX -> int32
    const int* msk = (const int*)d_in[2];
    int N = in_sizes[0] / (NB * 4);

    AllRand ar = make_allrand();

    float* out = (float*)d_out;
    size_t bn = (size_t)NB * (size_t)N;
    float* o_locs  = out;
    float* o_feats = out + bn * 4;
    float* o_org   = out + bn * 8;
    float* o_lbl   = out + bn * 15;
    float* o_nm    = out + bn * 16;
    float* o_off   = out + bn * 17;

    k_reduce<<<dim3(RB, NB), 256>>>(pts, N, ar);

    // PDL launches: dependent kernels may start while predecessor drains;
    // each calls cudaGridDependencySynchronize() before consuming its data.
    cudaLaunchAttribute attr[1];
    attr[0].id = cudaLaunchAttributeProgrammaticStreamSerialization;
    attr[0].val.programmaticStreamSerializationAllowed = 1;

    {
        cudaLaunchConfig_t cfg = {};
        cfg.gridDim = dim3(NB, 1, 1);
        cfg.blockDim = dim3(RB, 1, 1);
        cfg.attrs = attr;
        cfg.numAttrs = 1;
        cudaLaunchKernelEx(&cfg, k_mid, N, ar, o_off);
    }
    {
        cudaLaunchConfig_t cfg = {};
        cfg.gridDim = dim3((N + PPB - 1) / PPB, NB, 1);
        cfg.blockDim = dim3(FB, 1, 1);
        cfg.attrs = attr;
        cfg.numAttrs = 1;
        cudaLaunchKernelEx(&cfg, k_final, pts, tgt, msk, N, ar,
                           o_locs, o_feats, o_org, o_lbl, o_nm);
    }
    (void)n_in; (void)out_size;
}